// round 11
// baseline (speedup 1.0000x reference)
#include <cuda_runtime.h>
#include <cuda_fp16.h>
#include <mma.h>
#include <cstdint>

using namespace nvcuda;

#define N_TOK 4096
#define DIM   1024
#define NEXP  8
#define HDIM  2048
#define NSLOT 8192
#define PAD   128

// gemm tiling: block 128x128, 4 warps (2x2), warp tile 64x64, BK=32, 3 stages
#define TM 128
#define TN 128
#define BK 32
#define NTH 128
#define LDB 40            // smem row stride in halves (80B)
#define LDC 68            // epilogue fp32 row stride

#define STAGE_H (TM * LDB + TN * LDB)     // halves per stage (10240)
#define SMEM_BYTES (3 * STAGE_H * 2)      // 61440 B; epilogue overlay 34816 B fits

// ---------------- scratch (device globals) ----------------------------------
__device__ __align__(256) __half g_xh[(size_t)N_TOK * DIM];           // x in fp16
__device__ __align__(256) __half g_H [(size_t)(NSLOT + PAD) * HDIM];  // relu out fp16
__device__ __align__(256) __half g_w1h[(size_t)NEXP * HDIM * DIM];
__device__ __align__(256) __half g_w2h[(size_t)NEXP * DIM * HDIM];
__device__ __align__(256) float  g_O [(size_t)NSLOT * DIM];           // per-slot fc2 out
__device__ int   g_expert_tok[NSLOT];
__device__ float g_expert_w[NSLOT];
__device__ int   g_tok_slot[N_TOK * 2];
__device__ int   g_tok_e[N_TOK * 2];
__device__ float g_tok_w[N_TOK * 2];
__device__ int   g_counts[NEXP];
__device__ int   g_cursor[NEXP];
__device__ int   g_offsets[NEXP + 1];
__device__ float g_colsum[NEXP];
__device__ int   g_top1[NEXP];
__device__ int   g_nt;

// ---------------- helpers ---------------------------------------------------
__device__ __forceinline__ uint32_t smem_u32(const void* p) {
    return (uint32_t)__cvta_generic_to_shared(p);
}
__device__ __forceinline__ void cp_async16(uint32_t dst, const void* src) {
    asm volatile("cp.async.cg.shared.global [%0], [%1], 16;\n" :: "r"(dst), "l"(src));
}
__device__ __forceinline__ void cp_commit() {
    asm volatile("cp.async.commit_group;\n" ::: "memory");
}
template<int N> __device__ __forceinline__ void cp_wait() {
    asm volatile("cp.async.wait_group %0;\n" :: "n"(N) : "memory");
}

// ---------------- init -------------------------------------------------------
__global__ void init_kernel() {
    int t = threadIdx.x;
    if (t < NEXP) { g_counts[t] = 0; g_cursor[t] = 0; g_colsum[t] = 0.f; g_top1[t] = 0; }
    if (t == 0) g_nt = 0;
}

// ---------------- gate: 4 tokens/warp, fused x->fp16 conversion -------------
// 256 threads = 8 warps = 32 tokens per block; grid = N_TOK/32 = 128.
__global__ __launch_bounds__(256) void gate_kernel(
        const float* __restrict__ x,
        const unsigned char* __restrict__ pm,
        const float* __restrict__ gw,
        float* __restrict__ gate_out) {
    __shared__ float gw_s[NEXP * DIM];   // 32 KB

    const int tid = threadIdx.x;
    for (int i = tid; i < NEXP * DIM / 4; i += 256)
        ((float4*)gw_s)[i] = ((const float4*)gw)[i];
    __syncthreads();

    const int wid  = tid >> 5;
    const int lane = tid & 31;
    const int n0 = blockIdx.x * 32 + wid * 4;      // first of 4 tokens

    float acc[NEXP][4];
#pragma unroll
    for (int e = 0; e < NEXP; e++)
#pragma unroll
        for (int t = 0; t < 4; t++) acc[e][t] = 0.f;

#pragma unroll
    for (int i = 0; i < DIM / 128; i++) {          // 8 iters, float4 per lane
        const int d = i * 128 + lane * 4;
        float4 xv[4];
#pragma unroll
        for (int t = 0; t < 4; t++)
            xv[t] = *(const float4*)&x[(size_t)(n0 + t) * DIM + d];
        // fused fp16 conversion of x
#pragma unroll
        for (int t = 0; t < 4; t++) {
            __half2 h0 = __floats2half2_rn(xv[t].x, xv[t].y);
            __half2 h1 = __floats2half2_rn(xv[t].z, xv[t].w);
            uint2 o;
            o.x = *(uint32_t*)&h0;
            o.y = *(uint32_t*)&h1;
            *(uint2*)&g_xh[(size_t)(n0 + t) * DIM + d] = o;
        }
#pragma unroll
        for (int e = 0; e < NEXP; e++) {
            const float4 w4 = *(const float4*)&gw_s[e * DIM + d];
#pragma unroll
            for (int t = 0; t < 4; t++)
                acc[e][t] += xv[t].x * w4.x + xv[t].y * w4.y +
                             xv[t].z * w4.z + xv[t].w * w4.w;
        }
    }
    // butterfly reduce: every lane ends with the full sums
#pragma unroll
    for (int e = 0; e < NEXP; e++)
#pragma unroll
        for (int t = 0; t < 4; t++) {
#pragma unroll
            for (int o = 16; o > 0; o >>= 1)
                acc[e][t] += __shfl_xor_sync(0xffffffffu, acc[e][t], o);
        }

    if (lane < 4) {
        const int t = lane;
        const int n = n0 + t;
        bool masked = (pm[n] != 0);
        float m = acc[0][t];
#pragma unroll
        for (int e = 1; e < NEXP; e++) m = fmaxf(m, acc[e][t]);
        float gv[NEXP]; float s = 0.f;
#pragma unroll
        for (int e = 0; e < NEXP; e++) { gv[e] = expf(acc[e][t] - m); s += gv[e]; }
        float inv = 1.f / s;
#pragma unroll
        for (int e = 0; e < NEXP; e++) {
            gv[e] *= inv;
            if (masked) gv[e] = 0.f;
            gate_out[(size_t)n * NEXP + e] = gv[e];
        }
        int e1 = 0;
#pragma unroll
        for (int e = 1; e < NEXP; e++) if (gv[e] > gv[e1]) e1 = e;
        int e2 = -1;
#pragma unroll
        for (int e = 0; e < NEXP; e++) {
            if (e == e1) continue;
            if (e2 < 0 || gv[e] > gv[e2]) e2 = e;
        }
        float den = gv[e1] + gv[e2];
        if (den == 0.f) den = 1.f;
        g_tok_e[2 * n + 0] = e1;
        g_tok_e[2 * n + 1] = e2;
        g_tok_w[2 * n + 0] = gv[e1] / den;
        g_tok_w[2 * n + 1] = gv[e2] / den;
        atomicAdd(&g_counts[e1], 1);
        atomicAdd(&g_counts[e2], 1);
        if (!masked) { atomicAdd(&g_top1[e1], 1); atomicAdd(&g_nt, 1); }
#pragma unroll
        for (int e = 0; e < NEXP; e++) atomicAdd(&g_colsum[e], gv[e]);
    }
}

__global__ void offsets_kernel() {
    if (threadIdx.x == 0) {
        int off = 0;
        for (int e = 0; e < NEXP; e++) { g_offsets[e] = off; off += g_counts[e]; }
        g_offsets[NEXP] = off;
    }
}

__global__ void scatter_kernel() {
    int n = blockIdx.x * blockDim.x + threadIdx.x;
    if (n >= N_TOK) return;
#pragma unroll
    for (int s = 0; s < 2; s++) {
        int e = g_tok_e[2 * n + s];
        int pos = g_offsets[e] + atomicAdd(&g_cursor[e], 1);
        g_expert_tok[pos] = n;
        g_expert_w[pos]   = g_tok_w[2 * n + s];
        g_tok_slot[2 * n + s] = pos;
    }
}

// ---------------- weight fp32 -> fp16 conversion ----------------------------
template<int WHICH>
__global__ void conv_w_kernel(const float4* __restrict__ src, int n8) {
    uint4* dst = (uint4*)(WHICH == 0 ? g_w1h : g_w2h);
    int stride = gridDim.x * blockDim.x;
    for (int i = blockIdx.x * blockDim.x + threadIdx.x; i < n8; i += stride) {
        float4 v0 = src[2 * i];
        float4 v1 = src[2 * i + 1];
        __half2 h0 = __floats2half2_rn(v0.x, v0.y);
        __half2 h1 = __floats2half2_rn(v0.z, v0.w);
        __half2 h2 = __floats2half2_rn(v1.x, v1.y);
        __half2 h3 = __floats2half2_rn(v1.z, v1.w);
        uint4 o;
        o.x = *(uint32_t*)&h0;
        o.y = *(uint32_t*)&h1;
        o.z = *(uint32_t*)&h2;
        o.w = *(uint32_t*)&h3;
        dst[i] = o;
    }
}

// ---------------- grouped GEMM (fp16 wmma, 64x64 warp tile, 3-stage) --------
// MODE 0: g_H = half(relu(Xg @ w1h^T + b1))    KTOT=DIM,  NCOLS=HDIM  (A = gathered g_xh)
// MODE 1: g_O[slot] = w * (g_H @ w2h^T + b2)   KTOT=HDIM, NCOLS=DIM   (A = g_H)
template<int KTOT, int MODE>
__global__ __launch_bounds__(NTH, 2) void gemm_kernel(const float* __restrict__ bias) {
    const int e = blockIdx.z;
    const int off = g_offsets[e];
    const int cnt = g_offsets[e + 1] - off;
    const int row0 = blockIdx.y * TM;
    if (row0 >= cnt) return;
    const int n0 = blockIdx.x * TN;
    const int NCOLS = (MODE == 0) ? HDIM : DIM;

    extern __shared__ __align__(16) __half sh[];

    const int tid  = threadIdx.x;
    const int warp = tid >> 5;
    const int wm   = warp >> 1;          // 0..1 : 64-row strip
    const int wn   = warp & 1;           // 0..1 : 64-col strip

    const __half* Bbase = (MODE == 0) ? g_w1h : g_w2h;

    const __half* a_src[4];
    uint32_t a_off[4];
    const __half* b_src[4];
    uint32_t b_off[4];
#pragma unroll
    for (int i = 0; i < 4; i++) {
        int cid = tid + i * NTH;         // 0..511
        int r   = cid >> 2;              // 0..127
        int c8  = (cid & 3) * 8;         // 0,8,16,24 halves
        int slot = off + row0 + r;
        if (slot > NSLOT - 1) slot = NSLOT - 1;
        if (MODE == 0) {
            int tok = g_expert_tok[slot];
            a_src[i] = g_xh + (size_t)tok * DIM + c8;
        } else {
            a_src[i] = g_H + (size_t)slot * HDIM + c8;
        }
        a_off[i] = (uint32_t)((r * LDB + c8) * 2);
        b_src[i] = Bbase + (size_t)(e * NCOLS + n0 + r) * KTOT + c8;
        b_off[i] = (uint32_t)((TM * LDB + r * LDB + c8) * 2);
    }
    const uint32_t sbase = smem_u32(sh);
    const uint32_t STAGE_B = STAGE_H * 2;

    wmma::fragment<wmma::accumulator, 16, 16, 16, float> acc[4][4];
#pragma unroll
    for (int i = 0; i < 4; i++)
#pragma unroll
        for (int j = 0; j < 4; j++) wmma::fill_fragment(acc[i][j], 0.f);

    const int T = KTOT / BK;

#pragma unroll
    for (int s = 0; s < 2; s++) {
#pragma unroll
        for (int i = 0; i < 4; i++) {
            cp_async16(sbase + s * STAGE_B + a_off[i], a_src[i] + (size_t)s * BK);
            cp_async16(sbase + s * STAGE_B + b_off[i], b_src[i] + (size_t)s * BK);
        }
        cp_commit();
    }

    int buf = 0;
    for (int t = 0; t < T; t++) {
        if (t < T - 1) cp_wait<1>(); else cp_wait<0>();
        __syncthreads();

        if (t + 2 < T) {
            int pb = (buf + 2 >= 3) ? buf - 1 : buf + 2;
            uint32_t pbb = sbase + pb * STAGE_B;
#pragma unroll
            for (int i = 0; i < 4; i++) {
                cp_async16(pbb + a_off[i], a_src[i] + (size_t)(t + 2) * BK);
                cp_async16(pbb + b_off[i], b_src[i] + (size_t)(t + 2) * BK);
            }
            cp_commit();
        }

        const __half* As = sh + (size_t)buf * STAGE_H;
        const __half* Bs = As + TM * LDB;
#pragma unroll
        for (int kk = 0; kk < BK; kk += 16) {
            wmma::fragment<wmma::matrix_a, 16, 16, 16, half, wmma::row_major> af[4];
            wmma::fragment<wmma::matrix_b, 16, 16, 16, half, wmma::col_major> bf[4];
#pragma unroll
            for (int i = 0; i < 4; i++)
                wmma::load_matrix_sync(af[i], &As[(wm * 64 + i * 16) * LDB + kk], LDB);
#pragma unroll
            for (int j = 0; j < 4; j++)
                wmma::load_matrix_sync(bf[j], &Bs[(wn * 64 + j * 16) * LDB + kk], LDB);
#pragma unroll
            for (int i = 0; i < 4; i++)
#pragma unroll
                for (int j = 0; j < 4; j++)
                    wmma::mma_sync(acc[i][j], af[i], bf[j], acc[i][j]);
        }
        buf = (buf + 1 >= 3) ? 0 : buf + 1;
    }
    __syncthreads();

    float* Cs = (float*)sh;
#pragma unroll
    for (int p = 0; p < 2; p++) {
        if (wn == p) {
#pragma unroll
            for (int i = 0; i < 4; i++)
#pragma unroll
                for (int j = 0; j < 4; j++)
                    wmma::store_matrix_sync(&Cs[(wm * 64 + i * 16) * LDC + j * 16],
                                            acc[i][j], LDC, wmma::mem_row_major);
        }
        __syncthreads();

#pragma unroll
        for (int i = 0; i < 16; i++) {
            int idx4 = tid + i * NTH;
            int r    = idx4 >> 4;
            int c4   = (idx4 & 15) * 4;
            if (row0 + r < cnt) {
                int slot = off + row0 + r;
                int col  = n0 + p * 64 + c4;
                float4 v = *(const float4*)&Cs[r * LDC + c4];
                const float4 bv = *(const float4*)&bias[e * NCOLS + col];
                if (MODE == 0) {
                    __half2 h0 = __floats2half2_rn(fmaxf(v.x + bv.x, 0.f),
                                                   fmaxf(v.y + bv.y, 0.f));
                    __half2 h1 = __floats2half2_rn(fmaxf(v.z + bv.z, 0.f),
                                                   fmaxf(v.w + bv.w, 0.f));
                    uint2 o;
                    o.x = *(uint32_t*)&h0;
                    o.y = *(uint32_t*)&h1;
                    *(uint2*)&g_H[(size_t)slot * HDIM + col] = o;
                } else {
                    float w = g_expert_w[slot];
                    float4 o;
                    o.x = (v.x + bv.x) * w;
                    o.y = (v.y + bv.y) * w;
                    o.z = (v.z + bv.z) * w;
                    o.w = (v.w + bv.w) * w;
                    *(float4*)&g_O[(size_t)slot * DIM + col] = o;
                }
            }
        }
        __syncthreads();
    }
}

// ---------------- combine (+ lb_loss on block 0) -----------------------------
__global__ void combine_kernel(float* __restrict__ out, float* __restrict__ loss_out) {
    int n  = blockIdx.x;
    int c4 = threadIdx.x;
    if (n == 0 && c4 == 0) {
        float nt = (float)g_nt;
        float s = 0.f;
        for (int e = 0; e < NEXP; e++)
            s += ((float)g_top1[e] / nt) * (g_colsum[e] / nt);
        *loss_out = (float)NEXP * s;
    }
    int s0 = g_tok_slot[2 * n + 0];
    int s1 = g_tok_slot[2 * n + 1];
    float4 a = ((const float4*)(g_O + (size_t)s0 * DIM))[c4];
    float4 b = ((const float4*)(g_O + (size_t)s1 * DIM))[c4];
    float4 o;
    o.x = a.x + b.x; o.y = a.y + b.y; o.z = a.z + b.z; o.w = a.w + b.w;
    ((float4*)(out + (size_t)n * DIM))[c4] = o;
}

// ---------------- launch -----------------------------------------------------
extern "C" void kernel_launch(void* const* d_in, const int* in_sizes, int n_in,
                              void* d_out, int out_size) {
    const float*         x      = (const float*)d_in[0];
    const unsigned char* pm     = (const unsigned char*)d_in[1];
    const float*         gate_w = (const float*)d_in[2];
    const float*         fc1_w  = (const float*)d_in[3];
    const float*         fc1_b  = (const float*)d_in[4];
    const float*         fc2_w  = (const float*)d_in[5];
    const float*         fc2_b  = (const float*)d_in[6];
    (void)in_sizes; (void)n_in; (void)out_size;

    float* out      = (float*)d_out;
    float* gate_out = out + (size_t)N_TOK * DIM;
    float* loss_out = gate_out + (size_t)N_TOK * NEXP;

    // one-time host-side resources (no device memory involved)
    static cudaStream_t s1 = nullptr;
    static cudaEvent_t evFork = nullptr, evW0 = nullptr, evW1 = nullptr;
    if (s1 == nullptr) {
        cudaStreamCreateWithFlags(&s1, cudaStreamNonBlocking);
        cudaEventCreateWithFlags(&evFork, cudaEventDisableTiming);
        cudaEventCreateWithFlags(&evW0, cudaEventDisableTiming);
        cudaEventCreateWithFlags(&evW1, cudaEventDisableTiming);
        cudaFuncSetAttribute(gemm_kernel<DIM, 0>,
                             cudaFuncAttributeMaxDynamicSharedMemorySize, SMEM_BYTES);
        cudaFuncSetAttribute(gemm_kernel<HDIM, 1>,
                             cudaFuncAttributeMaxDynamicSharedMemorySize, SMEM_BYTES);
    }

    // fork: weight conversion on s1, independent of routing path
    cudaEventRecord(evFork, 0);
    cudaStreamWaitEvent(s1, evFork, 0);
    conv_w_kernel<0><<<2048, 256, 0, s1>>>((const float4*)fc1_w, NEXP * HDIM * DIM / 8);
    cudaEventRecord(evW0, s1);
    conv_w_kernel<1><<<2048, 256, 0, s1>>>((const float4*)fc2_w, NEXP * DIM * HDIM / 8);
    cudaEventRecord(evW1, s1);

    // main path
    init_kernel<<<1, 32>>>();
    gate_kernel<<<N_TOK / 32, 256>>>(x, pm, gate_w, gate_out);
    offsets_kernel<<<1, 32>>>();
    scatter_kernel<<<N_TOK / 256, 256>>>();

    cudaStreamWaitEvent(0, evW0, 0);     // join: GEMM1 needs w1h
    gemm_kernel<DIM, 0><<<dim3(HDIM / TN, NSLOT / TM, NEXP), NTH, SMEM_BYTES>>>(fc1_b);
    cudaStreamWaitEvent(0, evW1, 0);     // join: GEMM2 needs w2h
    gemm_kernel<HDIM, 1><<<dim3(DIM / TN, NSLOT / TM, NEXP), NTH, SMEM_BYTES>>>(fc2_b);
    combine_kernel<<<N_TOK, DIM / 4>>>(out, loss_out);
}

// round 12
// speedup vs baseline: 1.0331x; 1.0331x over previous
#include <cuda_runtime.h>
#include <cuda_fp16.h>
#include <mma.h>
#include <cstdint>

using namespace nvcuda;

#define N_TOK 4096
#define DIM   1024
#define NEXP  8
#define HDIM  2048
#define NSLOT 8192
#define PAD   128

// gemm tiling: block 128x128, 4 warps (2x2), warp tile 64x64, BK=32, 3 stages
#define TM 128
#define TN 128
#define BK 32
#define NTH 128
#define LDB 40            // smem row stride in halves (80B)
#define LDC 68            // epilogue fp32 row stride

#define STAGE_H (TM * LDB + TN * LDB)     // halves per stage (10240)
#define SMEM_BYTES (3 * STAGE_H * 2)      // 61440 B; epilogue overlay 34816 B fits

// ---------------- scratch (device globals) ----------------------------------
__device__ __align__(256) __half g_xh[(size_t)N_TOK * DIM];           // x in fp16
__device__ __align__(256) __half g_H [(size_t)(NSLOT + PAD) * HDIM];  // relu out fp16
__device__ __align__(256) __half g_w1h[(size_t)NEXP * HDIM * DIM];
__device__ __align__(256) __half g_w2h[(size_t)NEXP * DIM * HDIM];
__device__ __align__(256) float  g_O [(size_t)NSLOT * DIM];           // per-slot fc2 out
__device__ int   g_expert_tok[NSLOT];
__device__ float g_expert_w[NSLOT];
__device__ int   g_tok_slot[N_TOK * 2];
__device__ int   g_tok_e[N_TOK * 2];
__device__ float g_tok_w[N_TOK * 2];
__device__ int   g_counts[NEXP];
__device__ int   g_cursor[NEXP];
__device__ int   g_offsets[NEXP + 1];
__device__ float g_colsum[NEXP];
__device__ int   g_top1[NEXP];
__device__ int   g_nt;

// ---------------- helpers ---------------------------------------------------
__device__ __forceinline__ uint32_t smem_u32(const void* p) {
    return (uint32_t)__cvta_generic_to_shared(p);
}
__device__ __forceinline__ void cp_async16(uint32_t dst, const void* src) {
    asm volatile("cp.async.cg.shared.global [%0], [%1], 16;\n" :: "r"(dst), "l"(src));
}
__device__ __forceinline__ void cp_commit() {
    asm volatile("cp.async.commit_group;\n" ::: "memory");
}
template<int N> __device__ __forceinline__ void cp_wait() {
    asm volatile("cp.async.wait_group %0;\n" :: "n"(N) : "memory");
}

// ---------------- init -------------------------------------------------------
__global__ void init_kernel() {
    int t = threadIdx.x;
    if (t < NEXP) { g_counts[t] = 0; g_cursor[t] = 0; g_colsum[t] = 0.f; g_top1[t] = 0; }
    if (t == 0) g_nt = 0;
}

// ---------------- gate: 1 token/warp, 4-deep load batching ------------------
// 256 threads = 8 warps = 8 tokens per block; grid = N_TOK/8 = 512.
__global__ __launch_bounds__(256) void gate_kernel(
        const float* __restrict__ x,
        const unsigned char* __restrict__ pm,
        const float* __restrict__ gw,
        float* __restrict__ gate_out) {
    __shared__ float gw_s[NEXP * DIM];   // 32 KB

    const int tid = threadIdx.x;
    for (int i = tid; i < NEXP * DIM / 4; i += 256)
        ((float4*)gw_s)[i] = ((const float4*)gw)[i];
    __syncthreads();

    const int wid  = tid >> 5;
    const int lane = tid & 31;
    const int n = blockIdx.x * 8 + wid;
    const float* xr = x + (size_t)n * DIM;

    float acc[NEXP];
#pragma unroll
    for (int e = 0; e < NEXP; e++) acc[e] = 0.f;

    // 8 segments processed as 2 groups of 4 with hoisted loads (MLP=4)
#pragma unroll
    for (int g = 0; g < 2; g++) {
        float4 xv[4];
#pragma unroll
        for (int j = 0; j < 4; j++) {
            const int d = (g * 4 + j) * 128 + lane * 4;
            xv[j] = *(const float4*)&xr[d];
        }
#pragma unroll
        for (int j = 0; j < 4; j++) {
            const int d = (g * 4 + j) * 128 + lane * 4;
            // fused fp16 conversion of x
            __half2 h0 = __floats2half2_rn(xv[j].x, xv[j].y);
            __half2 h1 = __floats2half2_rn(xv[j].z, xv[j].w);
            uint2 o;
            o.x = *(uint32_t*)&h0;
            o.y = *(uint32_t*)&h1;
            *(uint2*)&g_xh[(size_t)n * DIM + d] = o;
#pragma unroll
            for (int e = 0; e < NEXP; e++) {
                const float4 w4 = *(const float4*)&gw_s[e * DIM + d];
                acc[e] += xv[j].x * w4.x + xv[j].y * w4.y +
                          xv[j].z * w4.z + xv[j].w * w4.w;
            }
        }
    }
#pragma unroll
    for (int e = 0; e < NEXP; e++) {
#pragma unroll
        for (int o = 16; o > 0; o >>= 1)
            acc[e] += __shfl_xor_sync(0xffffffffu, acc[e], o);
    }

    if (lane == 0) {
        bool masked = (pm[n] != 0);
        float m = acc[0];
#pragma unroll
        for (int e = 1; e < NEXP; e++) m = fmaxf(m, acc[e]);
        float gv[NEXP]; float s = 0.f;
#pragma unroll
        for (int e = 0; e < NEXP; e++) { gv[e] = expf(acc[e] - m); s += gv[e]; }
        float inv = 1.f / s;
#pragma unroll
        for (int e = 0; e < NEXP; e++) {
            gv[e] *= inv;
            if (masked) gv[e] = 0.f;
            gate_out[(size_t)n * NEXP + e] = gv[e];
        }
        int e1 = 0;
#pragma unroll
        for (int e = 1; e < NEXP; e++) if (gv[e] > gv[e1]) e1 = e;
        int e2 = -1;
#pragma unroll
        for (int e = 0; e < NEXP; e++) {
            if (e == e1) continue;
            if (e2 < 0 || gv[e] > gv[e2]) e2 = e;
        }
        float den = gv[e1] + gv[e2];
        if (den == 0.f) den = 1.f;
        g_tok_e[2 * n + 0] = e1;
        g_tok_e[2 * n + 1] = e2;
        g_tok_w[2 * n + 0] = gv[e1] / den;
        g_tok_w[2 * n + 1] = gv[e2] / den;
        atomicAdd(&g_counts[e1], 1);
        atomicAdd(&g_counts[e2], 1);
        if (!masked) { atomicAdd(&g_top1[e1], 1); atomicAdd(&g_nt, 1); }
#pragma unroll
        for (int e = 0; e < NEXP; e++) atomicAdd(&g_colsum[e], gv[e]);
    }
}

__global__ void offsets_kernel() {
    if (threadIdx.x == 0) {
        int off = 0;
        for (int e = 0; e < NEXP; e++) { g_offsets[e] = off; off += g_counts[e]; }
        g_offsets[NEXP] = off;
    }
}

__global__ void scatter_kernel() {
    int n = blockIdx.x * blockDim.x + threadIdx.x;
    if (n >= N_TOK) return;
#pragma unroll
    for (int s = 0; s < 2; s++) {
        int e = g_tok_e[2 * n + s];
        int pos = g_offsets[e] + atomicAdd(&g_cursor[e], 1);
        g_expert_tok[pos] = n;
        g_expert_w[pos]   = g_tok_w[2 * n + s];
        g_tok_slot[2 * n + s] = pos;
    }
}

// ---------------- weight fp32 -> fp16 conversion ----------------------------
template<int WHICH>
__global__ void conv_w_kernel(const float4* __restrict__ src, int n8) {
    uint4* dst = (uint4*)(WHICH == 0 ? g_w1h : g_w2h);
    int stride = gridDim.x * blockDim.x;
    for (int i = blockIdx.x * blockDim.x + threadIdx.x; i < n8; i += stride) {
        float4 v0 = src[2 * i];
        float4 v1 = src[2 * i + 1];
        __half2 h0 = __floats2half2_rn(v0.x, v0.y);
        __half2 h1 = __floats2half2_rn(v0.z, v0.w);
        __half2 h2 = __floats2half2_rn(v1.x, v1.y);
        __half2 h3 = __floats2half2_rn(v1.z, v1.w);
        uint4 o;
        o.x = *(uint32_t*)&h0;
        o.y = *(uint32_t*)&h1;
        o.z = *(uint32_t*)&h2;
        o.w = *(uint32_t*)&h3;
        dst[i] = o;
    }
}

// ---------------- grouped GEMM (fp16 wmma, 64x64 warp tile, 3-stage) --------
// MODE 0: g_H = half(relu(Xg @ w1h^T + b1))    KTOT=DIM,  NCOLS=HDIM  (A = gathered g_xh)
// MODE 1: g_O[slot] = w * (g_H @ w2h^T + b2)   KTOT=HDIM, NCOLS=DIM   (A = g_H)
template<int KTOT, int MODE>
__global__ __launch_bounds__(NTH, 2) void gemm_kernel(const float* __restrict__ bias) {
    const int e = blockIdx.z;
    const int off = g_offsets[e];
    const int cnt = g_offsets[e + 1] - off;
    const int row0 = blockIdx.y * TM;
    if (row0 >= cnt) return;
    const int n0 = blockIdx.x * TN;
    const int NCOLS = (MODE == 0) ? HDIM : DIM;

    extern __shared__ __align__(16) __half sh[];

    const int tid  = threadIdx.x;
    const int warp = tid >> 5;
    const int wm   = warp >> 1;          // 0..1 : 64-row strip
    const int wn   = warp & 1;           // 0..1 : 64-col strip

    const __half* Bbase = (MODE == 0) ? g_w1h : g_w2h;

    const __half* a_src[4];
    uint32_t a_off[4];
    const __half* b_src[4];
    uint32_t b_off[4];
#pragma unroll
    for (int i = 0; i < 4; i++) {
        int cid = tid + i * NTH;         // 0..511
        int r   = cid >> 2;              // 0..127
        int c8  = (cid & 3) * 8;         // 0,8,16,24 halves
        int slot = off + row0 + r;
        if (slot > NSLOT - 1) slot = NSLOT - 1;
        if (MODE == 0) {
            int tok = g_expert_tok[slot];
            a_src[i] = g_xh + (size_t)tok * DIM + c8;
        } else {
            a_src[i] = g_H + (size_t)slot * HDIM + c8;
        }
        a_off[i] = (uint32_t)((r * LDB + c8) * 2);
        b_src[i] = Bbase + (size_t)(e * NCOLS + n0 + r) * KTOT + c8;
        b_off[i] = (uint32_t)((TM * LDB + r * LDB + c8) * 2);
    }
    const uint32_t sbase = smem_u32(sh);
    const uint32_t STAGE_B = STAGE_H * 2;

    wmma::fragment<wmma::accumulator, 16, 16, 16, float> acc[4][4];
#pragma unroll
    for (int i = 0; i < 4; i++)
#pragma unroll
        for (int j = 0; j < 4; j++) wmma::fill_fragment(acc[i][j], 0.f);

    const int T = KTOT / BK;

#pragma unroll
    for (int s = 0; s < 2; s++) {
#pragma unroll
        for (int i = 0; i < 4; i++) {
            cp_async16(sbase + s * STAGE_B + a_off[i], a_src[i] + (size_t)s * BK);
            cp_async16(sbase + s * STAGE_B + b_off[i], b_src[i] + (size_t)s * BK);
        }
        cp_commit();
    }

    int buf = 0;
    for (int t = 0; t < T; t++) {
        if (t < T - 1) cp_wait<1>(); else cp_wait<0>();
        __syncthreads();

        if (t + 2 < T) {
            int pb = (buf + 2 >= 3) ? buf - 1 : buf + 2;
            uint32_t pbb = sbase + pb * STAGE_B;
#pragma unroll
            for (int i = 0; i < 4; i++) {
                cp_async16(pbb + a_off[i], a_src[i] + (size_t)(t + 2) * BK);
                cp_async16(pbb + b_off[i], b_src[i] + (size_t)(t + 2) * BK);
            }
            cp_commit();
        }

        const __half* As = sh + (size_t)buf * STAGE_H;
        const __half* Bs = As + TM * LDB;
#pragma unroll
        for (int kk = 0; kk < BK; kk += 16) {
            wmma::fragment<wmma::matrix_a, 16, 16, 16, half, wmma::row_major> af[4];
            wmma::fragment<wmma::matrix_b, 16, 16, 16, half, wmma::col_major> bf[4];
#pragma unroll
            for (int i = 0; i < 4; i++)
                wmma::load_matrix_sync(af[i], &As[(wm * 64 + i * 16) * LDB + kk], LDB);
#pragma unroll
            for (int j = 0; j < 4; j++)
                wmma::load_matrix_sync(bf[j], &Bs[(wn * 64 + j * 16) * LDB + kk], LDB);
#pragma unroll
            for (int i = 0; i < 4; i++)
#pragma unroll
                for (int j = 0; j < 4; j++)
                    wmma::mma_sync(acc[i][j], af[i], bf[j], acc[i][j]);
        }
        buf = (buf + 1 >= 3) ? 0 : buf + 1;
    }
    __syncthreads();

    float* Cs = (float*)sh;
#pragma unroll
    for (int p = 0; p < 2; p++) {
        if (wn == p) {
#pragma unroll
            for (int i = 0; i < 4; i++)
#pragma unroll
                for (int j = 0; j < 4; j++)
                    wmma::store_matrix_sync(&Cs[(wm * 64 + i * 16) * LDC + j * 16],
                                            acc[i][j], LDC, wmma::mem_row_major);
        }
        __syncthreads();

#pragma unroll
        for (int i = 0; i < 16; i++) {
            int idx4 = tid + i * NTH;
            int r    = idx4 >> 4;
            int c4   = (idx4 & 15) * 4;
            if (row0 + r < cnt) {
                int slot = off + row0 + r;
                int col  = n0 + p * 64 + c4;
                float4 v = *(const float4*)&Cs[r * LDC + c4];
                const float4 bv = *(const float4*)&bias[e * NCOLS + col];
                if (MODE == 0) {
                    __half2 h0 = __floats2half2_rn(fmaxf(v.x + bv.x, 0.f),
                                                   fmaxf(v.y + bv.y, 0.f));
                    __half2 h1 = __floats2half2_rn(fmaxf(v.z + bv.z, 0.f),
                                                   fmaxf(v.w + bv.w, 0.f));
                    uint2 o;
                    o.x = *(uint32_t*)&h0;
                    o.y = *(uint32_t*)&h1;
                    *(uint2*)&g_H[(size_t)slot * HDIM + col] = o;
                } else {
                    float w = g_expert_w[slot];
                    float4 o;
                    o.x = (v.x + bv.x) * w;
                    o.y = (v.y + bv.y) * w;
                    o.z = (v.z + bv.z) * w;
                    o.w = (v.w + bv.w) * w;
                    *(float4*)&g_O[(size_t)slot * DIM + col] = o;
                }
            }
        }
        __syncthreads();
    }
}

// ---------------- combine (+ lb_loss on block 0) -----------------------------
__global__ void combine_kernel(float* __restrict__ out, float* __restrict__ loss_out) {
    int n  = blockIdx.x;
    int c4 = threadIdx.x;
    if (n == 0 && c4 == 0) {
        float nt = (float)g_nt;
        float s = 0.f;
        for (int e = 0; e < NEXP; e++)
            s += ((float)g_top1[e] / nt) * (g_colsum[e] / nt);
        *loss_out = (float)NEXP * s;
    }
    int s0 = g_tok_slot[2 * n + 0];
    int s1 = g_tok_slot[2 * n + 1];
    float4 a = ((const float4*)(g_O + (size_t)s0 * DIM))[c4];
    float4 b = ((const float4*)(g_O + (size_t)s1 * DIM))[c4];
    float4 o;
    o.x = a.x + b.x; o.y = a.y + b.y; o.z = a.z + b.z; o.w = a.w + b.w;
    ((float4*)(out + (size_t)n * DIM))[c4] = o;
}

// ---------------- launch -----------------------------------------------------
extern "C" void kernel_launch(void* const* d_in, const int* in_sizes, int n_in,
                              void* d_out, int out_size) {
    const float*         x      = (const float*)d_in[0];
    const unsigned char* pm     = (const unsigned char*)d_in[1];
    const float*         gate_w = (const float*)d_in[2];
    const float*         fc1_w  = (const float*)d_in[3];
    const float*         fc1_b  = (const float*)d_in[4];
    const float*         fc2_w  = (const float*)d_in[5];
    const float*         fc2_b  = (const float*)d_in[6];
    (void)in_sizes; (void)n_in; (void)out_size;

    float* out      = (float*)d_out;
    float* gate_out = out + (size_t)N_TOK * DIM;
    float* loss_out = gate_out + (size_t)N_TOK * NEXP;

    // one-time host-side resources (no device memory involved)
    static cudaStream_t s1 = nullptr;
    static cudaEvent_t evFork = nullptr, evW0 = nullptr, evW1 = nullptr;
    if (s1 == nullptr) {
        cudaStreamCreateWithFlags(&s1, cudaStreamNonBlocking);
        cudaEventCreateWithFlags(&evFork, cudaEventDisableTiming);
        cudaEventCreateWithFlags(&evW0, cudaEventDisableTiming);
        cudaEventCreateWithFlags(&evW1, cudaEventDisableTiming);
        cudaFuncSetAttribute(gemm_kernel<DIM, 0>,
                             cudaFuncAttributeMaxDynamicSharedMemorySize, SMEM_BYTES);
        cudaFuncSetAttribute(gemm_kernel<HDIM, 1>,
                             cudaFuncAttributeMaxDynamicSharedMemorySize, SMEM_BYTES);
    }

    // fork: weight conversion on s1, independent of routing path
    cudaEventRecord(evFork, 0);
    cudaStreamWaitEvent(s1, evFork, 0);
    conv_w_kernel<0><<<2048, 256, 0, s1>>>((const float4*)fc1_w, NEXP * HDIM * DIM / 8);
    cudaEventRecord(evW0, s1);
    conv_w_kernel<1><<<2048, 256, 0, s1>>>((const float4*)fc2_w, NEXP * DIM * HDIM / 8);
    cudaEventRecord(evW1, s1);

    // main path
    init_kernel<<<1, 32>>>();
    gate_kernel<<<N_TOK / 8, 256>>>(x, pm, gate_w, gate_out);
    offsets_kernel<<<1, 32>>>();
    scatter_kernel<<<N_TOK / 256, 256>>>();

    cudaStreamWaitEvent(0, evW0, 0);     // join: GEMM1 needs w1h
    gemm_kernel<DIM, 0><<<dim3(HDIM / TN, NSLOT / TM, NEXP), NTH, SMEM_BYTES>>>(fc1_b);
    cudaStreamWaitEvent(0, evW1, 0);     // join: GEMM2 needs w2h
    gemm_kernel<HDIM, 1><<<dim3(DIM / TN, NSLOT / TM, NEXP), NTH, SMEM_BYTES>>>(fc2_b);
    combine_kernel<<<N_TOK, DIM / 4>>>(out, loss_out);
}

// round 13
// speedup vs baseline: 1.1526x; 1.1157x over previous
#include <cuda_runtime.h>
#include <cuda_fp16.h>
#include <mma.h>
#include <cstdint>

using namespace nvcuda;

#define N_TOK 4096
#define DIM   1024
#define NEXP  8
#define HDIM  2048
#define NSLOT 8192
#define PAD   128

// gemm tiling: block 128x128, 4 warps (2x2), warp tile 64x64, BK=32, 3 stages
#define TM 128
#define TN 128
#define BK 32
#define NTH 128
#define LDB 40            // smem row stride in halves (80B)
#define LDC 68            // epilogue fp32 row stride

#define STAGE_H (TM * LDB + TN * LDB)     // halves per stage (10240)
#define SMEM_BYTES (3 * STAGE_H * 2)      // 61440 B; epilogue overlay 34816 B fits

// ---------------- scratch (device globals) ----------------------------------
__device__ __align__(256) __half g_xh[(size_t)N_TOK * DIM];           // x in fp16
__device__ __align__(256) __half g_H [(size_t)(NSLOT + PAD) * HDIM];  // relu out fp16
__device__ __align__(256) __half g_w1h[(size_t)NEXP * HDIM * DIM];
__device__ __align__(256) __half g_w2h[(size_t)NEXP * DIM * HDIM];
__device__ int   g_expert_tok[NSLOT];
__device__ float g_expert_w[NSLOT];
__device__ int   g_tok_e[N_TOK * 2];
__device__ float g_tok_w[N_TOK * 2];
__device__ int   g_counts[NEXP];
__device__ int   g_cursor[NEXP];
__device__ int   g_offsets[NEXP + 1];
__device__ float g_colsum[NEXP];
__device__ int   g_top1[NEXP];
__device__ int   g_nt;

// ---------------- helpers ---------------------------------------------------
__device__ __forceinline__ uint32_t smem_u32(const void* p) {
    return (uint32_t)__cvta_generic_to_shared(p);
}
__device__ __forceinline__ void cp_async16(uint32_t dst, const void* src) {
    asm volatile("cp.async.cg.shared.global [%0], [%1], 16;\n" :: "r"(dst), "l"(src));
}
__device__ __forceinline__ void cp_commit() {
    asm volatile("cp.async.commit_group;\n" ::: "memory");
}
template<int N> __device__ __forceinline__ void cp_wait() {
    asm volatile("cp.async.wait_group %0;\n" :: "n"(N) : "memory");
}

// ---------------- init -------------------------------------------------------
__global__ void init_kernel() {
    int t = threadIdx.x;
    if (t < NEXP) { g_counts[t] = 0; g_cursor[t] = 0; g_colsum[t] = 0.f; g_top1[t] = 0; }
    if (t == 0) g_nt = 0;
}

// ---------------- gate: fused x->fp16, block-aggregated stats ---------------
// 256 threads = 8 warps = 8 tokens per block; grid = N_TOK/8 = 512.
__global__ __launch_bounds__(256) void gate_kernel(
        const float* __restrict__ x,
        const unsigned char* __restrict__ pm,
        const float* __restrict__ gw,
        float* __restrict__ gate_out) {
    __shared__ float gw_s[NEXP * DIM];   // 32 KB
    __shared__ float s_colsum[NEXP];
    __shared__ int   s_counts[NEXP];
    __shared__ int   s_top1[NEXP];
    __shared__ int   s_nt;

    const int tid = threadIdx.x;
    if (tid < NEXP) { s_colsum[tid] = 0.f; s_counts[tid] = 0; s_top1[tid] = 0; }
    if (tid == 0) s_nt = 0;
    for (int i = tid; i < NEXP * DIM / 4; i += 256)
        ((float4*)gw_s)[i] = ((const float4*)gw)[i];
    __syncthreads();

    const int wid  = tid >> 5;
    const int lane = tid & 31;
    const int n = blockIdx.x * 8 + wid;
    const float* xr = x + (size_t)n * DIM;

    float acc[NEXP];
#pragma unroll
    for (int e = 0; e < NEXP; e++) acc[e] = 0.f;

#pragma unroll
    for (int i = 0; i < DIM / 128; i++) {          // 8 iters, float4 per lane
        const int d = i * 128 + lane * 4;
        float4 v = *(const float4*)&xr[d];
        __half2 h0 = __floats2half2_rn(v.x, v.y);
        __half2 h1 = __floats2half2_rn(v.z, v.w);
        uint2 o;
        o.x = *(uint32_t*)&h0;
        o.y = *(uint32_t*)&h1;
        *(uint2*)&g_xh[(size_t)n * DIM + d] = o;
#pragma unroll
        for (int e = 0; e < NEXP; e++) {
            const float4 w4 = *(const float4*)&gw_s[e * DIM + d];
            acc[e] += v.x * w4.x + v.y * w4.y + v.z * w4.z + v.w * w4.w;
        }
    }
#pragma unroll
    for (int e = 0; e < NEXP; e++) {
#pragma unroll
        for (int o = 16; o > 0; o >>= 1)
            acc[e] += __shfl_xor_sync(0xffffffffu, acc[e], o);
    }

    if (lane == 0) {
        bool masked = (pm[n] != 0);
        float m = acc[0];
#pragma unroll
        for (int e = 1; e < NEXP; e++) m = fmaxf(m, acc[e]);
        float gv[NEXP]; float s = 0.f;
#pragma unroll
        for (int e = 0; e < NEXP; e++) { gv[e] = expf(acc[e] - m); s += gv[e]; }
        float inv = 1.f / s;
#pragma unroll
        for (int e = 0; e < NEXP; e++) {
            gv[e] *= inv;
            if (masked) gv[e] = 0.f;
            gate_out[(size_t)n * NEXP + e] = gv[e];
        }
        int e1 = 0;
#pragma unroll
        for (int e = 1; e < NEXP; e++) if (gv[e] > gv[e1]) e1 = e;
        int e2 = -1;
#pragma unroll
        for (int e = 0; e < NEXP; e++) {
            if (e == e1) continue;
            if (e2 < 0 || gv[e] > gv[e2]) e2 = e;
        }
        float den = gv[e1] + gv[e2];
        if (den == 0.f) den = 1.f;
        g_tok_e[2 * n + 0] = e1;
        g_tok_e[2 * n + 1] = e2;
        g_tok_w[2 * n + 0] = gv[e1] / den;
        g_tok_w[2 * n + 1] = gv[e2] / den;
        // block-local aggregation (fast shared atomics)
        atomicAdd(&s_counts[e1], 1);
        atomicAdd(&s_counts[e2], 1);
        if (!masked) { atomicAdd(&s_top1[e1], 1); atomicAdd(&s_nt, 1); }
#pragma unroll
        for (int e = 0; e < NEXP; e++) atomicAdd(&s_colsum[e], gv[e]);
    }
    __syncthreads();
    if (tid < NEXP) {
        atomicAdd(&g_colsum[tid], s_colsum[tid]);
        atomicAdd(&g_counts[tid], s_counts[tid]);
        atomicAdd(&g_top1[tid], s_top1[tid]);
    }
    if (tid == 0) atomicAdd(&g_nt, s_nt);
}

// ---------------- offsets (+ lb_loss) ----------------------------------------
__global__ void offsets_kernel(float* __restrict__ loss_out) {
    if (threadIdx.x == 0) {
        int off = 0;
        for (int e = 0; e < NEXP; e++) { g_offsets[e] = off; off += g_counts[e]; }
        g_offsets[NEXP] = off;
        float nt = (float)g_nt;
        float s = 0.f;
        for (int e = 0; e < NEXP; e++)
            s += ((float)g_top1[e] / nt) * (g_colsum[e] / nt);
        *loss_out = (float)NEXP * s;
    }
}

__global__ void scatter_kernel() {
    int n = blockIdx.x * blockDim.x + threadIdx.x;
    if (n >= N_TOK) return;
#pragma unroll
    for (int s = 0; s < 2; s++) {
        int e = g_tok_e[2 * n + s];
        int pos = g_offsets[e] + atomicAdd(&g_cursor[e], 1);
        g_expert_tok[pos] = n;
        g_expert_w[pos]   = g_tok_w[2 * n + s];
    }
}

// ---------------- weight fp32 -> fp16 conversion ----------------------------
template<int WHICH>
__global__ void conv_w_kernel(const float4* __restrict__ src, int n8) {
    uint4* dst = (uint4*)(WHICH == 0 ? g_w1h : g_w2h);
    int stride = gridDim.x * blockDim.x;
    for (int i = blockIdx.x * blockDim.x + threadIdx.x; i < n8; i += stride) {
        float4 v0 = src[2 * i];
        float4 v1 = src[2 * i + 1];
        __half2 h0 = __floats2half2_rn(v0.x, v0.y);
        __half2 h1 = __floats2half2_rn(v0.z, v0.w);
        __half2 h2 = __floats2half2_rn(v1.x, v1.y);
        __half2 h3 = __floats2half2_rn(v1.z, v1.w);
        uint4 o;
        o.x = *(uint32_t*)&h0;
        o.y = *(uint32_t*)&h1;
        o.z = *(uint32_t*)&h2;
        o.w = *(uint32_t*)&h3;
        dst[i] = o;
    }
}

// ---------------- grouped GEMM (fp16 wmma, 64x64 warp tile, 3-stage) --------
// MODE 0: g_H = half(relu(Xg @ w1h^T + b1))          KTOT=DIM,  NCOLS=HDIM
// MODE 1: out[tok] += w * (g_H @ w2h^T + b2) atomics  KTOT=HDIM, NCOLS=DIM
template<int KTOT, int MODE>
__global__ __launch_bounds__(NTH, 2) void gemm_kernel(const float* __restrict__ bias,
                                                      float* __restrict__ outp) {
    const int e = blockIdx.z;
    const int off = g_offsets[e];
    const int cnt = g_offsets[e + 1] - off;
    const int row0 = blockIdx.y * TM;
    if (row0 >= cnt) return;
    const int n0 = blockIdx.x * TN;
    const int NCOLS = (MODE == 0) ? HDIM : DIM;

    extern __shared__ __align__(16) __half sh[];

    const int tid  = threadIdx.x;
    const int warp = tid >> 5;
    const int wm   = warp >> 1;          // 0..1 : 64-row strip
    const int wn   = warp & 1;           // 0..1 : 64-col strip

    const __half* Bbase = (MODE == 0) ? g_w1h : g_w2h;

    const __half* a_src[4];
    uint32_t a_off[4];
    const __half* b_src[4];
    uint32_t b_off[4];
#pragma unroll
    for (int i = 0; i < 4; i++) {
        int cid = tid + i * NTH;         // 0..511
        int r   = cid >> 2;              // 0..127
        int c8  = (cid & 3) * 8;         // 0,8,16,24 halves
        int slot = off + row0 + r;
        if (slot > NSLOT - 1) slot = NSLOT - 1;
        if (MODE == 0) {
            int tok = g_expert_tok[slot];
            a_src[i] = g_xh + (size_t)tok * DIM + c8;
        } else {
            a_src[i] = g_H + (size_t)slot * HDIM + c8;
        }
        a_off[i] = (uint32_t)((r * LDB + c8) * 2);
        b_src[i] = Bbase + (size_t)(e * NCOLS + n0 + r) * KTOT + c8;
        b_off[i] = (uint32_t)((TM * LDB + r * LDB + c8) * 2);
    }
    const uint32_t sbase = smem_u32(sh);
    const uint32_t STAGE_B = STAGE_H * 2;

    wmma::fragment<wmma::accumulator, 16, 16, 16, float> acc[4][4];
#pragma unroll
    for (int i = 0; i < 4; i++)
#pragma unroll
        for (int j = 0; j < 4; j++) wmma::fill_fragment(acc[i][j], 0.f);

    const int T = KTOT / BK;

#pragma unroll
    for (int s = 0; s < 2; s++) {
#pragma unroll
        for (int i = 0; i < 4; i++) {
            cp_async16(sbase + s * STAGE_B + a_off[i], a_src[i] + (size_t)s * BK);
            cp_async16(sbase + s * STAGE_B + b_off[i], b_src[i] + (size_t)s * BK);
        }
        cp_commit();
    }

    int buf = 0;
    for (int t = 0; t < T; t++) {
        if (t < T - 1) cp_wait<1>(); else cp_wait<0>();
        __syncthreads();

        if (t + 2 < T) {
            int pb = (buf + 2 >= 3) ? buf - 1 : buf + 2;
            uint32_t pbb = sbase + pb * STAGE_B;
#pragma unroll
            for (int i = 0; i < 4; i++) {
                cp_async16(pbb + a_off[i], a_src[i] + (size_t)(t + 2) * BK);
                cp_async16(pbb + b_off[i], b_src[i] + (size_t)(t + 2) * BK);
            }
            cp_commit();
        }

        const __half* As = sh + (size_t)buf * STAGE_H;
        const __half* Bs = As + TM * LDB;
#pragma unroll
        for (int kk = 0; kk < BK; kk += 16) {
            wmma::fragment<wmma::matrix_a, 16, 16, 16, half, wmma::row_major> af[4];
            wmma::fragment<wmma::matrix_b, 16, 16, 16, half, wmma::col_major> bf[4];
#pragma unroll
            for (int i = 0; i < 4; i++)
                wmma::load_matrix_sync(af[i], &As[(wm * 64 + i * 16) * LDB + kk], LDB);
#pragma unroll
            for (int j = 0; j < 4; j++)
                wmma::load_matrix_sync(bf[j], &Bs[(wn * 64 + j * 16) * LDB + kk], LDB);
#pragma unroll
            for (int i = 0; i < 4; i++)
#pragma unroll
                for (int j = 0; j < 4; j++)
                    wmma::mma_sync(acc[i][j], af[i], bf[j], acc[i][j]);
        }
        buf = (buf + 1 >= 3) ? 0 : buf + 1;
    }
    __syncthreads();

    float* Cs = (float*)sh;
#pragma unroll
    for (int p = 0; p < 2; p++) {
        if (wn == p) {
#pragma unroll
            for (int i = 0; i < 4; i++)
#pragma unroll
                for (int j = 0; j < 4; j++)
                    wmma::store_matrix_sync(&Cs[(wm * 64 + i * 16) * LDC + j * 16],
                                            acc[i][j], LDC, wmma::mem_row_major);
        }
        __syncthreads();

#pragma unroll
        for (int i = 0; i < 16; i++) {
            int idx4 = tid + i * NTH;
            int r    = idx4 >> 4;
            int c4   = (idx4 & 15) * 4;
            if (row0 + r < cnt) {
                int slot = off + row0 + r;
                int col  = n0 + p * 64 + c4;
                float4 v = *(const float4*)&Cs[r * LDC + c4];
                const float4 bv = *(const float4*)&bias[e * NCOLS + col];
                if (MODE == 0) {
                    __half2 h0 = __floats2half2_rn(fmaxf(v.x + bv.x, 0.f),
                                                   fmaxf(v.y + bv.y, 0.f));
                    __half2 h1 = __floats2half2_rn(fmaxf(v.z + bv.z, 0.f),
                                                   fmaxf(v.w + bv.w, 0.f));
                    uint2 o;
                    o.x = *(uint32_t*)&h0;
                    o.y = *(uint32_t*)&h1;
                    *(uint2*)&g_H[(size_t)slot * HDIM + col] = o;
                } else {
                    int tok = g_expert_tok[slot];
                    float w = g_expert_w[slot];
                    float* o = &outp[(size_t)tok * DIM + col];
                    // exactly 2 commutative fp32 adds per element -> deterministic
                    atomicAdd(o + 0, (v.x + bv.x) * w);
                    atomicAdd(o + 1, (v.y + bv.y) * w);
                    atomicAdd(o + 2, (v.z + bv.z) * w);
                    atomicAdd(o + 3, (v.w + bv.w) * w);
                }
            }
        }
        __syncthreads();
    }
}

// ---------------- launch -----------------------------------------------------
extern "C" void kernel_launch(void* const* d_in, const int* in_sizes, int n_in,
                              void* d_out, int out_size) {
    const float*         x      = (const float*)d_in[0];
    const unsigned char* pm     = (const unsigned char*)d_in[1];
    const float*         gate_w = (const float*)d_in[2];
    const float*         fc1_w  = (const float*)d_in[3];
    const float*         fc1_b  = (const float*)d_in[4];
    const float*         fc2_w  = (const float*)d_in[5];
    const float*         fc2_b  = (const float*)d_in[6];
    (void)in_sizes; (void)n_in; (void)out_size;

    float* out      = (float*)d_out;
    float* gate_out = out + (size_t)N_TOK * DIM;
    float* loss_out = gate_out + (size_t)N_TOK * NEXP;

    // one-time host-side resources (no device memory involved)
    static cudaStream_t s1 = nullptr;
    static cudaEvent_t evFork = nullptr, evW0 = nullptr, evW1 = nullptr;
    if (s1 == nullptr) {
        cudaStreamCreateWithFlags(&s1, cudaStreamNonBlocking);
        cudaEventCreateWithFlags(&evFork, cudaEventDisableTiming);
        cudaEventCreateWithFlags(&evW0, cudaEventDisableTiming);
        cudaEventCreateWithFlags(&evW1, cudaEventDisableTiming);
        cudaFuncSetAttribute(gemm_kernel<DIM, 0>,
                             cudaFuncAttributeMaxDynamicSharedMemorySize, SMEM_BYTES);
        cudaFuncSetAttribute(gemm_kernel<HDIM, 1>,
                             cudaFuncAttributeMaxDynamicSharedMemorySize, SMEM_BYTES);
    }

    // fork: out-zeroing + weight conversion on s1 (independent of routing path)
    cudaEventRecord(evFork, 0);
    cudaStreamWaitEvent(s1, evFork, 0);
    cudaMemsetAsync(out, 0, (size_t)N_TOK * DIM * sizeof(float), s1);
    conv_w_kernel<0><<<2048, 256, 0, s1>>>((const float4*)fc1_w, NEXP * HDIM * DIM / 8);
    cudaEventRecord(evW0, s1);
    conv_w_kernel<1><<<2048, 256, 0, s1>>>((const float4*)fc2_w, NEXP * DIM * HDIM / 8);
    cudaEventRecord(evW1, s1);

    // main path
    init_kernel<<<1, 32>>>();
    gate_kernel<<<N_TOK / 8, 256>>>(x, pm, gate_w, gate_out);
    offsets_kernel<<<1, 32>>>(loss_out);
    scatter_kernel<<<N_TOK / 256, 256>>>();

    cudaStreamWaitEvent(0, evW0, 0);     // join: GEMM1 needs w1h (and memset done)
    gemm_kernel<DIM, 0><<<dim3(HDIM / TN, NSLOT / TM, NEXP), NTH, SMEM_BYTES>>>(fc1_b, nullptr);
    cudaStreamWaitEvent(0, evW1, 0);     // join: GEMM2 needs w2h
    gemm_kernel<HDIM, 1><<<dim3(DIM / TN, NSLOT / TM, NEXP), NTH, SMEM_BYTES>>>(fc2_b, out);
}